// round 1
// baseline (speedup 1.0000x reference)
#include <cuda_runtime.h>
#include <cuda_bf16.h>

// ---------------- problem constants / scratch capacities ----------------
#define MAXB 8
#define MAXN 200000
#define KPRE 512
#define GCAP 2048
#define MAXDET 300
#define NBIN 65536
#define SCORE_THR 0.05f
#define IOU_THR 0.5f

// ---------------- device scratch (static, no runtime alloc) ----------------
__device__ float               d_score[MAXB * MAXN];
__device__ int                 d_label[MAXB * MAXN];
__device__ unsigned int        d_hist1[MAXB * NBIN];
__device__ unsigned int        d_hist2[MAXB * NBIN];
__device__ int                 d_b1[MAXB];
__device__ int                 d_rem[MAXB];
__device__ unsigned int        d_T[MAXB];
__device__ unsigned long long  d_gath[MAXB * GCAP];
__device__ int                 d_cnt[MAXB];

// ---------------- K0: zero histograms + counters ----------------
__global__ void zeroK() {
    int i = blockIdx.x * blockDim.x + threadIdx.x;
    int total = MAXB * NBIN;
    if (i < total) { d_hist1[i] = 0u; d_hist2[i] = 0u; }
    if (i < MAXB) d_cnt[i] = 0;
}

// ---------------- K1: per-anchor class max/argmax + level-1 histogram ----------------
__global__ void scoreK(const float* __restrict__ cls, int N, int C) {
    int b = blockIdx.y;
    int n = blockIdx.x * blockDim.x + threadIdx.x;
    if (n >= N) return;
    size_t base = (size_t)b * N + n;
    const float* row = cls + base * C;
    float best = -1e30f; int bi = 0;
    if ((C & 3) == 0 && ((((size_t)row) & 15) == 0)) {
        const float4* r4 = (const float4*)row;
        int K4 = C >> 2;
        for (int k = 0; k < K4; k++) {
            float4 v = r4[k];
            if (v.x > best) { best = v.x; bi = 4*k;     }
            if (v.y > best) { best = v.y; bi = 4*k + 1; }
            if (v.z > best) { best = v.z; bi = 4*k + 2; }
            if (v.w > best) { best = v.w; bi = 4*k + 3; }
        }
    } else {
        best = row[0]; bi = 0;
        for (int k = 1; k < C; k++) { float v = row[k]; if (v > best) { best = v; bi = k; } }
    }
    d_score[base] = best;
    d_label[base] = bi;
    if (best > SCORE_THR)
        atomicAdd(&d_hist1[(b << 16) + (__float_as_uint(best) >> 16)], 1u);
}

// ---------------- descending-bin selection helper (256-thread block) ----------------
__device__ void find_desc_bin(const unsigned int* h, int target, int* res_bin, int* res_rem) {
    __shared__ int chunkS[256];
    __shared__ int binsS[256];
    __shared__ int s_c, s_cum;
    int t = threadIdx.x;
    int s = 0;
    const unsigned int* hp = h + t * 256;
    for (int k = 0; k < 256; k++) s += (int)hp[k];
    chunkS[t] = s;
    __syncthreads();
    if (t == 0) {
        int cum = 0, c = -1;
        for (int cc = 255; cc >= 0; cc--) {
            if (cum + chunkS[cc] >= target) { c = cc; break; }
            cum += chunkS[cc];
        }
        s_c = c; s_cum = cum;
    }
    __syncthreads();
    int c = s_c;
    if (c < 0) {                        // total < target
        if (t == 0) { *res_bin = -1; *res_rem = 0; }
        return;
    }
    binsS[t] = (int)h[c * 256 + t];
    __syncthreads();
    if (t == 0) {
        int cum = s_cum; int bin = 0;
        for (int bb = 255; bb >= 0; bb--) {
            if (cum + binsS[bb] >= target) { bin = c * 256 + bb; break; }
            cum += binsS[bb];
        }
        *res_bin = bin; *res_rem = target - cum;
    }
}

// ---------------- K2: pick level-1 bin containing the 512th score ----------------
__global__ void selectBin1K() {
    int b = blockIdx.x;
    find_desc_bin(d_hist1 + b * NBIN, KPRE, &d_b1[b], &d_rem[b]);
}

// ---------------- K3: level-2 histogram (low 16 bits) for items in bin1 ----------------
__global__ void hist2K(int N) {
    int b = blockIdx.y;
    int n = blockIdx.x * blockDim.x + threadIdx.x;
    if (n >= N) return;
    float s = d_score[(size_t)b * N + n];
    if (s > SCORE_THR) {
        unsigned key = __float_as_uint(s);
        if ((int)(key >> 16) == d_b1[b])
            atomicAdd(&d_hist2[(b << 16) + (key & 0xFFFFu)], 1u);
    }
}

// ---------------- K4: exact 32-bit threshold key ----------------
__global__ void selectBin2K() {
    int b = blockIdx.x;
    __shared__ int sb, sr;
    if (d_b1[b] < 0) {                       // fewer than 512 valid -> take all
        if (threadIdx.x == 0) d_T[b] = 1u;
        return;
    }
    find_desc_bin(d_hist2 + b * NBIN, d_rem[b], &sb, &sr);
    if (threadIdx.x == 0)
        d_T[b] = (((unsigned)d_b1[b]) << 16) | (unsigned)sb;
}

// ---------------- K5: gather candidates with key >= T ----------------
__global__ void gatherK(int N) {
    int b = blockIdx.y;
    int n = blockIdx.x * blockDim.x + threadIdx.x;
    if (n >= N) return;
    float s = d_score[(size_t)b * N + n];
    if (s > SCORE_THR) {
        unsigned key = __float_as_uint(s);
        if (key >= d_T[b]) {
            int p = atomicAdd(&d_cnt[b], 1);
            if (p < GCAP)
                d_gath[b * GCAP + p] = ((unsigned long long)key << 32) | (unsigned)(~(unsigned)n);
        }
    }
}

// ---------------- K6: sort candidates, decode+clip boxes, NMS, write output ----------------
__global__ __launch_bounds__(1024, 1) void finalizeK(
    const float* __restrict__ anchors, const float* __restrict__ regs,
    const float* __restrict__ sizes, float* __restrict__ out, int N, int B)
{
    int b = blockIdx.x;
    int tid = threadIdx.x;

    // shared layout (mask region aliases the sort buffer):
    // [0,32768)            mask[512][16]  /  arr[2048] (u64, first 16384 bytes)
    // [32768,40960)        sBox  float4[512]
    // [40960,43008)        sArea float[512]
    // [43008,45056)        sScore float[512]
    // [45056,47104)        sLabel int[512]
    // [47104,47168)        keepW u32[16]
    // [47168,47296)        warpCnt int[32]
    __shared__ __align__(16) unsigned char sm[47296];
    unsigned int*       mask  = (unsigned int*)sm;
    unsigned long long* arr   = (unsigned long long*)sm;
    float4*             sBox  = (float4*)(sm + 32768);
    float*              sArea = (float*) (sm + 40960);
    float*              sScore= (float*) (sm + 43008);
    int*                sLabel= (int*)   (sm + 45056);
    unsigned int*       keepW = (unsigned int*)(sm + 47104);
    int*                warpCnt = (int*)(sm + 47168);

    int cnt = d_cnt[b]; if (cnt > GCAP) cnt = GCAP;
    int nv  = cnt < KPRE ? cnt : KPRE;

    // ---- load gathered (key,~idx) pairs, pad with 0 ----
    for (int i = tid; i < GCAP; i += blockDim.x)
        arr[i] = (i < cnt) ? d_gath[b * GCAP + i] : 0ull;
    __syncthreads();

    // ---- bitonic sort, 2048 elems descending (key desc, idx asc) ----
    for (int k = 2; k <= GCAP; k <<= 1) {
        for (int j = k >> 1; j >= 1; j >>= 1) {
            int i = ((tid & ~(j - 1)) << 1) | (tid & (j - 1));
            int p = i + j;
            bool up = (i & k) != 0;               // ascending segment
            unsigned long long a = arr[i], c2 = arr[p];
            bool sw = up ? (a > c2) : (a < c2);
            if (sw) { arr[i] = c2; arr[p] = a; }
            __syncthreads();
        }
    }

    // ---- decode + clip boxes for top nv; default-fill output with -1 ----
    float H = sizes[b * 2 + 0], W = sizes[b * 2 + 1];
    if (tid < nv) {
        unsigned long long v = arr[tid];
        unsigned key = (unsigned)(v >> 32);
        int idx = (int)(~(unsigned)v);
        size_t off = (size_t)b * N + idx;
        float4 a = ((const float4*)anchors)[off];
        float4 r = ((const float4*)regs)[off];
        float w = a.z - a.x, h = a.w - a.y;
        float cx = a.x + 0.5f * w, cy = a.y + 0.5f * h;
        float dx = r.x * 0.1f, dy = r.y * 0.1f, dw = r.z * 0.2f, dh = r.w * 0.2f;
        float pcx = cx + dx * w, pcy = cy + dy * h;
        float pw = expf(dw) * w, ph = expf(dh) * h;
        float x1 = pcx - 0.5f * pw, y1 = pcy - 0.5f * ph;
        float x2 = pcx + 0.5f * pw, y2 = pcy + 0.5f * ph;
        x1 = fminf(fmaxf(x1, 0.f), W); x2 = fminf(fmaxf(x2, 0.f), W);
        y1 = fminf(fmaxf(y1, 0.f), H); y2 = fminf(fmaxf(y2, 0.f), H);
        sBox[tid]  = make_float4(x1, y1, x2, y2);
        sArea[tid] = (x2 - x1) * (y2 - y1);
        sScore[tid]= __uint_as_float(key);
        sLabel[tid]= d_label[off];
    }
    float* outB = out;
    float* outS = out + (size_t)B * MAXDET * 4;
    float* outL = out + (size_t)B * MAXDET * 5;
    if (tid < MAXDET) {
        ((float4*)outB)[b * MAXDET + tid] = make_float4(-1.f, -1.f, -1.f, -1.f);
        outS[b * MAXDET + tid] = -1.f;
        outL[b * MAXDET + tid] = -1.f;
    }
    __syncthreads();   // arr reads done -> mask may now overwrite that region

    // ---- parallel IoU suppression bitmask: mask[i] has bit j set (j>i) iff iou>thr ----
    if (tid < KPRE) {
        float4 bi; float ai = 0.f;
        bool v = tid < nv;
        if (v) { bi = sBox[tid]; ai = sArea[tid]; }
        for (int w = 0; w < 16; w++) {
            unsigned word = 0;
            if (v) {
                int j0 = w * 32, j1 = j0 + 32;
                if (j1 > nv) j1 = nv;
                int js = (tid + 1 > j0) ? tid + 1 : j0;
                for (int j = js; j < j1; j++) {
                    float4 bj = sBox[j];
                    float lx = fmaxf(bi.x, bj.x), ly = fmaxf(bi.y, bj.y);
                    float rx = fminf(bi.z, bj.z), ry = fminf(bi.w, bj.w);
                    float iw = fmaxf(rx - lx, 0.f), ih = fmaxf(ry - ly, 0.f);
                    float inter = iw * ih;
                    float iou = inter / (ai + sArea[j] - inter + 1e-9f);
                    if (iou > IOU_THR) word |= 1u << (j & 31);
                }
            }
            mask[tid * 16 + w] = word;
        }
    }
    __syncthreads();

    // ---- warp-serial greedy resolution, keep-words live in registers ----
    if (tid < 32) {
        unsigned kw = 0;
        if (tid < 16) {
            int full = nv >> 5, rem = nv & 31;
            kw = (tid < full) ? 0xFFFFFFFFu
               : ((tid == full && rem) ? ((1u << rem) - 1u) : 0u);
        }
        for (int i = 0; i < nv; i++) {
            unsigned ow = __shfl_sync(0xFFFFFFFFu, kw, i >> 5);
            if ((ow >> (i & 31)) & 1u) {
                if (tid < 16) kw &= ~mask[i * 16 + tid];
            }
        }
        if (tid < 16) keepW[tid] = kw;
    }
    __syncthreads();

    // ---- compact kept candidates (score order) into first <=300 slots ----
    bool kept = false;
    if (tid < nv) kept = (keepW[tid >> 5] >> (tid & 31)) & 1u;
    unsigned wm = __ballot_sync(0xFFFFFFFFu, kept);
    int w = tid >> 5, lane = tid & 31;
    if (lane == 0) warpCnt[w] = __popc(wm);
    __syncthreads();
    if (kept) {
        int prefix = 0;
        for (int i = 0; i < w; i++) prefix += warpCnt[i];
        int pos = prefix + __popc(wm & ((1u << lane) - 1u));
        if (pos < MAXDET) {
            ((float4*)outB)[b * MAXDET + pos] = sBox[tid];
            outS[b * MAXDET + pos] = sScore[tid];
            outL[b * MAXDET + pos] = (float)sLabel[tid];
        }
    }
}

// ---------------- launch ----------------
extern "C" void kernel_launch(void* const* d_in, const int* in_sizes, int n_in,
                              void* d_out, int out_size) {
    const float* anchors = (const float*)d_in[0];
    const float* regs    = (const float*)d_in[1];
    const float* cls     = (const float*)d_in[2];
    const float* sizes   = (const float*)d_in[3];

    int B = in_sizes[3] / 2;            // sizes is [B,2]
    if (B <= 0 || B > MAXB) B = MAXB;
    int N = in_sizes[0] / (B * 4);      // anchors [B,N,4]
    long long clsElems = (long long)in_sizes[2];
    int C = (int)(clsElems / ((long long)B * N));

    dim3 gridBN((N + 255) / 256, B);

    zeroK<<<(MAXB * NBIN + 255) / 256, 256>>>();
    scoreK<<<gridBN, 256>>>(cls, N, C);
    selectBin1K<<<B, 256>>>();
    hist2K<<<gridBN, 256>>>(N);
    selectBin2K<<<B, 256>>>();
    gatherK<<<gridBN, 256>>>(N);
    finalizeK<<<B, 1024>>>(anchors, regs, sizes, (float*)d_out, N, B);
}

// round 2
// speedup vs baseline: 1.5010x; 1.5010x over previous
#include <cuda_runtime.h>
#include <cuda_bf16.h>

// ---------------- problem constants / scratch capacities ----------------
#define MAXB 8
#define MAXN 200000
#define KPRE 512
#define GCAP 2048
#define MAXDET 300
#define NBIN 65536
#define HCOPY 16
#define SCORE_THR 0.05f
#define IOU_THR 0.5f

// ---------------- device scratch (static, no runtime alloc) ----------------
__device__ float               d_score[MAXB * MAXN];
__device__ int                 d_label[MAXB * MAXN];
__device__ unsigned int        d_hist1[MAXB * HCOPY * NBIN];   // privatized copies
__device__ unsigned int        d_hist1s[MAXB * NBIN];          // summed
__device__ unsigned int        d_hist2[MAXB * NBIN];
__device__ int                 d_b1[MAXB];
__device__ int                 d_rem[MAXB];
__device__ unsigned int        d_T[MAXB];
__device__ unsigned long long  d_gath[MAXB * GCAP];
__device__ int                 d_cnt[MAXB];

// ---------------- K0: zero histograms + counters ----------------
__global__ void zeroK() {
    int i = blockIdx.x * blockDim.x + threadIdx.x;
    if (i < MAXB * HCOPY * NBIN) d_hist1[i] = 0u;
    if (i < MAXB * NBIN)         d_hist2[i] = 0u;
    if (i < MAXB)                d_cnt[i] = 0;
}

// ---------------- K1 (fast, C==80): 4 threads/row, coalesced ----------------
__global__ void scoreK80(const float* __restrict__ cls, int N) {
    int t   = blockIdx.x * blockDim.x + threadIdx.x;
    int row = t >> 2;
    int sub = t & 3;
    int b   = blockIdx.y;
    bool valid = row < N;
    int rclamp = valid ? row : (N - 1);
    const float4* r4 = (const float4*)(cls + ((size_t)b * N + rclamp) * 80);

    float best = -1e30f; int bi = 0;
    #pragma unroll
    for (int k = 0; k < 5; k++) {
        float4 v = r4[sub + 4 * k];
        int e = (sub + 4 * k) * 4;
        if (v.x > best) { best = v.x; bi = e;     }
        if (v.y > best) { best = v.y; bi = e + 1; }
        if (v.z > best) { best = v.z; bi = e + 2; }
        if (v.w > best) { best = v.w; bi = e + 3; }
    }
    // reduce across the 4 lanes of this row (keep smallest index on ties)
    #pragma unroll
    for (int off = 2; off >= 1; off >>= 1) {
        float ov = __shfl_down_sync(0xFFFFFFFFu, best, off);
        int   oi = __shfl_down_sync(0xFFFFFFFFu, bi,   off);
        if (ov > best || (ov == best && oi < bi)) { best = ov; bi = oi; }
    }
    if (sub == 0 && valid) {
        size_t base = (size_t)b * N + row;
        d_score[base] = best;
        d_label[base] = bi;
        if (best > SCORE_THR) {
            int copy = blockIdx.x & (HCOPY - 1);
            atomicAdd(&d_hist1[(((b << 4) + copy) << 16) + (__float_as_uint(best) >> 16)], 1u);
        }
    }
}

// ---------------- K1 (generic fallback) ----------------
__global__ void scoreKgen(const float* __restrict__ cls, int N, int C) {
    int b = blockIdx.y;
    int n = blockIdx.x * blockDim.x + threadIdx.x;
    if (n >= N) return;
    size_t base = (size_t)b * N + n;
    const float* row = cls + base * C;
    float best = row[0]; int bi = 0;
    for (int k = 1; k < C; k++) { float v = row[k]; if (v > best) { best = v; bi = k; } }
    d_score[base] = best;
    d_label[base] = bi;
    if (best > SCORE_THR) {
        int copy = blockIdx.x & (HCOPY - 1);
        atomicAdd(&d_hist1[(((b << 4) + copy) << 16) + (__float_as_uint(best) >> 16)], 1u);
    }
}

// ---------------- K1b: sum privatized histogram copies (coalesced) ----------------
__global__ void reduceHistK() {
    int i = blockIdx.x * blockDim.x + threadIdx.x;   // over MAXB * NBIN
    if (i >= MAXB * NBIN) return;
    int b = i >> 16, bin = i & 0xFFFF;
    unsigned s = 0;
    #pragma unroll
    for (int c = 0; c < HCOPY; c++)
        s += d_hist1[(((b << 4) + c) << 16) + bin];
    d_hist1s[i] = s;
}

// ---------------- descending-bin selection helper (256-thread block) ----------------
__device__ void find_desc_bin(const unsigned int* h, int target, int* res_bin, int* res_rem) {
    __shared__ int chunkS[256];
    __shared__ int binsS[256];
    __shared__ int s_c, s_cum;
    int t = threadIdx.x;
    int s = 0;
    const unsigned int* hp = h + t * 256;
    for (int k = 0; k < 256; k++) s += (int)hp[k];
    chunkS[t] = s;
    __syncthreads();
    if (t == 0) {
        int cum = 0, c = -1;
        for (int cc = 255; cc >= 0; cc--) {
            if (cum + chunkS[cc] >= target) { c = cc; break; }
            cum += chunkS[cc];
        }
        s_c = c; s_cum = cum;
    }
    __syncthreads();
    int c = s_c;
    if (c < 0) {
        if (t == 0) { *res_bin = -1; *res_rem = 0; }
        return;
    }
    binsS[t] = (int)h[c * 256 + t];
    __syncthreads();
    if (t == 0) {
        int cum = s_cum; int bin = 0;
        for (int bb = 255; bb >= 0; bb--) {
            if (cum + binsS[bb] >= target) { bin = c * 256 + bb; break; }
            cum += binsS[bb];
        }
        *res_bin = bin; *res_rem = target - cum;
    }
}

// ---------------- K2: pick level-1 bin containing the 512th score ----------------
__global__ void selectBin1K() {
    int b = blockIdx.x;
    find_desc_bin(d_hist1s + b * NBIN, KPRE, &d_b1[b], &d_rem[b]);
}

// ---------------- K3: level-2 histogram (low 16 bits) for items in bin1 ----------------
__global__ void hist2K(int N) {
    int b = blockIdx.y;
    int n = blockIdx.x * blockDim.x + threadIdx.x;
    if (n >= N) return;
    float s = d_score[(size_t)b * N + n];
    if (s > SCORE_THR) {
        unsigned key = __float_as_uint(s);
        if ((int)(key >> 16) == d_b1[b])
            atomicAdd(&d_hist2[(b << 16) + (key & 0xFFFFu)], 1u);
    }
}

// ---------------- K4: exact 32-bit threshold key ----------------
__global__ void selectBin2K() {
    int b = blockIdx.x;
    __shared__ int sb, sr;
    if (d_b1[b] < 0) {                       // fewer than 512 valid -> take all
        if (threadIdx.x == 0) d_T[b] = 1u;
        return;
    }
    find_desc_bin(d_hist2 + b * NBIN, d_rem[b], &sb, &sr);
    if (threadIdx.x == 0)
        d_T[b] = (((unsigned)d_b1[b]) << 16) | (unsigned)sb;
}

// ---------------- K5: gather candidates with key >= T ----------------
__global__ void gatherK(int N) {
    int b = blockIdx.y;
    int n = blockIdx.x * blockDim.x + threadIdx.x;
    if (n >= N) return;
    float s = d_score[(size_t)b * N + n];
    if (s > SCORE_THR) {
        unsigned key = __float_as_uint(s);
        if (key >= d_T[b]) {
            int p = atomicAdd(&d_cnt[b], 1);
            if (p < GCAP)
                d_gath[b * GCAP + p] = ((unsigned long long)key << 32) | (unsigned)(~(unsigned)n);
        }
    }
}

// ---------------- K6: sort candidates, decode+clip boxes, NMS, write output ----------------
__global__ __launch_bounds__(1024, 1) void finalizeK(
    const float* __restrict__ anchors, const float* __restrict__ regs,
    const float* __restrict__ sizes, float* __restrict__ out, int N, int B)
{
    int b = blockIdx.x;
    int tid = threadIdx.x;

    // shared layout (mask region aliases the sort buffer):
    __shared__ __align__(16) unsigned char sm[47296];
    unsigned int*       mask  = (unsigned int*)sm;            // [512][16]
    unsigned long long* arr   = (unsigned long long*)sm;      // [2048]
    float4*             sBox  = (float4*)(sm + 32768);
    float*              sArea = (float*) (sm + 40960);
    float*              sScore= (float*) (sm + 43008);
    int*                sLabel= (int*)   (sm + 45056);
    unsigned int*       keepW = (unsigned int*)(sm + 47104);
    int*                warpCnt = (int*)(sm + 47168);

    int cnt = d_cnt[b]; if (cnt > GCAP) cnt = GCAP;
    int nv  = cnt < KPRE ? cnt : KPRE;
    int S   = (cnt <= 512) ? 512 : ((cnt <= 1024) ? 1024 : 2048);

    for (int i = tid; i < S; i += blockDim.x)
        arr[i] = (i < cnt) ? d_gath[b * GCAP + i] : 0ull;
    __syncthreads();

    // bitonic sort, S elems descending (key desc, idx asc)
    for (int k = 2; k <= S; k <<= 1) {
        for (int j = k >> 1; j >= 1; j >>= 1) {
            if (tid < (S >> 1)) {
                int i = ((tid & ~(j - 1)) << 1) | (tid & (j - 1));
                int p = i + j;
                bool up = (i & k) != 0;
                unsigned long long a = arr[i], c2 = arr[p];
                bool sw = up ? (a > c2) : (a < c2);
                if (sw) { arr[i] = c2; arr[p] = a; }
            }
            __syncthreads();
        }
    }

    // decode + clip boxes for top nv; default-fill output with -1
    float H = sizes[b * 2 + 0], W = sizes[b * 2 + 1];
    if (tid < nv) {
        unsigned long long v = arr[tid];
        unsigned key = (unsigned)(v >> 32);
        int idx = (int)(~(unsigned)v);
        size_t off = (size_t)b * N + idx;
        float4 a = ((const float4*)anchors)[off];
        float4 r = ((const float4*)regs)[off];
        float w = a.z - a.x, h = a.w - a.y;
        float cx = a.x + 0.5f * w, cy = a.y + 0.5f * h;
        float dx = r.x * 0.1f, dy = r.y * 0.1f, dw = r.z * 0.2f, dh = r.w * 0.2f;
        float pcx = cx + dx * w, pcy = cy + dy * h;
        float pw = expf(dw) * w, ph = expf(dh) * h;
        float x1 = pcx - 0.5f * pw, y1 = pcy - 0.5f * ph;
        float x2 = pcx + 0.5f * pw, y2 = pcy + 0.5f * ph;
        x1 = fminf(fmaxf(x1, 0.f), W); x2 = fminf(fmaxf(x2, 0.f), W);
        y1 = fminf(fmaxf(y1, 0.f), H); y2 = fminf(fmaxf(y2, 0.f), H);
        sBox[tid]  = make_float4(x1, y1, x2, y2);
        sArea[tid] = (x2 - x1) * (y2 - y1);
        sScore[tid]= __uint_as_float(key);
        sLabel[tid]= d_label[off];
    }
    float* outB = out;
    float* outS = out + (size_t)B * MAXDET * 4;
    float* outL = out + (size_t)B * MAXDET * 5;
    if (tid < MAXDET) {
        ((float4*)outB)[b * MAXDET + tid] = make_float4(-1.f, -1.f, -1.f, -1.f);
        outS[b * MAXDET + tid] = -1.f;
        outL[b * MAXDET + tid] = -1.f;
    }
    __syncthreads();   // arr reads done -> mask may now overwrite that region

    // parallel IoU suppression bitmask
    if (tid < KPRE) {
        float4 bi; float ai = 0.f;
        bool v = tid < nv;
        if (v) { bi = sBox[tid]; ai = sArea[tid]; }
        for (int w = 0; w < 16; w++) {
            unsigned word = 0;
            if (v) {
                int j0 = w * 32, j1 = j0 + 32;
                if (j1 > nv) j1 = nv;
                int js = (tid + 1 > j0) ? tid + 1 : j0;
                for (int j = js; j < j1; j++) {
                    float4 bj = sBox[j];
                    float lx = fmaxf(bi.x, bj.x), ly = fmaxf(bi.y, bj.y);
                    float rx = fminf(bi.z, bj.z), ry = fminf(bi.w, bj.w);
                    float iw = fmaxf(rx - lx, 0.f), ih = fmaxf(ry - ly, 0.f);
                    float inter = iw * ih;
                    float iou = inter / (ai + sArea[j] - inter + 1e-9f);
                    if (iou > IOU_THR) word |= 1u << (j & 31);
                }
            }
            mask[tid * 16 + w] = word;
        }
    }
    __syncthreads();

    // warp-serial greedy resolution, keep-words live in registers
    if (tid < 32) {
        unsigned kw = 0;
        if (tid < 16) {
            int full = nv >> 5, rem = nv & 31;
            kw = (tid < full) ? 0xFFFFFFFFu
               : ((tid == full && rem) ? ((1u << rem) - 1u) : 0u);
        }
        for (int i = 0; i < nv; i++) {
            unsigned ow = __shfl_sync(0xFFFFFFFFu, kw, i >> 5);
            if ((ow >> (i & 31)) & 1u) {
                if (tid < 16) kw &= ~mask[i * 16 + tid];
            }
        }
        if (tid < 16) keepW[tid] = kw;
    }
    __syncthreads();

    // compact kept candidates (score order) into first <=300 slots
    bool kept = false;
    if (tid < nv) kept = (keepW[tid >> 5] >> (tid & 31)) & 1u;
    unsigned wm = __ballot_sync(0xFFFFFFFFu, kept);
    int w = tid >> 5, lane = tid & 31;
    if (lane == 0) warpCnt[w] = __popc(wm);
    __syncthreads();
    if (kept) {
        int prefix = 0;
        for (int i = 0; i < w; i++) prefix += warpCnt[i];
        int pos = prefix + __popc(wm & ((1u << lane) - 1u));
        if (pos < MAXDET) {
            ((float4*)outB)[b * MAXDET + pos] = sBox[tid];
            outS[b * MAXDET + pos] = sScore[tid];
            outL[b * MAXDET + pos] = (float)sLabel[tid];
        }
    }
}

// ---------------- launch ----------------
extern "C" void kernel_launch(void* const* d_in, const int* in_sizes, int n_in,
                              void* d_out, int out_size) {
    const float* anchors = (const float*)d_in[0];
    const float* regs    = (const float*)d_in[1];
    const float* cls     = (const float*)d_in[2];
    const float* sizes   = (const float*)d_in[3];

    int B = in_sizes[3] / 2;            // sizes is [B,2]
    if (B <= 0 || B > MAXB) B = MAXB;
    int N = in_sizes[0] / (B * 4);      // anchors [B,N,4]
    long long clsElems = (long long)in_sizes[2];
    int C = (int)(clsElems / ((long long)B * N));

    dim3 gridBN((N + 255) / 256, B);

    zeroK<<<(MAXB * HCOPY * NBIN + 255) / 256, 256>>>();
    if (C == 80) {
        dim3 gridS(((N * 4) + 255) / 256, B);
        scoreK80<<<gridS, 256>>>(cls, N);
    } else {
        scoreKgen<<<gridBN, 256>>>(cls, N, C);
    }
    reduceHistK<<<(MAXB * NBIN + 255) / 256, 256>>>();
    selectBin1K<<<B, 256>>>();
    hist2K<<<gridBN, 256>>>(N);
    selectBin2K<<<B, 256>>>();
    gatherK<<<gridBN, 256>>>(N);
    finalizeK<<<B, 1024>>>(anchors, regs, sizes, (float*)d_out, N, B);
}

// round 3
// speedup vs baseline: 2.8260x; 1.8828x over previous
#include <cuda_runtime.h>
#include <cuda_bf16.h>

// ---------------- problem constants / scratch capacities ----------------
#define MAXB 8
#define MAXN 200000
#define KPRE 512
#define GCAP 2048
#define MAXDET 300
#define NBIN 65536
#define HCOPY 8
#define SCORE_THR 0.05f
#define IOU_THR 0.5f

// ---------------- device scratch (static, no runtime alloc) ----------------
__device__ float               d_score[MAXB * MAXN];
__device__ int                 d_label[MAXB * MAXN];
__device__ unsigned int        d_hist1[MAXB * HCOPY * NBIN];   // privatized copies
__device__ unsigned int        d_hist1s[MAXB * NBIN];          // summed
__device__ unsigned int        d_hist2[MAXB * NBIN];
__device__ int                 d_b1[MAXB];
__device__ int                 d_rem[MAXB];
__device__ unsigned int        d_T[MAXB];
__device__ unsigned long long  d_gath[MAXB * GCAP];
__device__ int                 d_cnt[MAXB];

// ---------------- K0: zero histograms + counters ----------------
__global__ void zeroK() {
    int i = blockIdx.x * blockDim.x + threadIdx.x;
    if (i < MAXB * HCOPY * NBIN) d_hist1[i] = 0u;
    if (i < MAXB * NBIN)         d_hist2[i] = 0u;
    if (i < MAXB)                d_cnt[i] = 0;
}

// ---------------- K1 (fast, C==80): 4 threads/row, coalesced ----------------
__global__ void scoreK80(const float* __restrict__ cls, int N) {
    int t   = blockIdx.x * blockDim.x + threadIdx.x;
    int row = t >> 2;
    int sub = t & 3;
    int b   = blockIdx.y;
    bool valid = row < N;
    int rclamp = valid ? row : (N - 1);
    const float4* r4 = (const float4*)(cls + ((size_t)b * N + rclamp) * 80);

    float best = -1e30f; int bi = 0;
    #pragma unroll
    for (int k = 0; k < 5; k++) {
        float4 v = r4[sub + 4 * k];
        int e = (sub + 4 * k) * 4;
        if (v.x > best) { best = v.x; bi = e;     }
        if (v.y > best) { best = v.y; bi = e + 1; }
        if (v.z > best) { best = v.z; bi = e + 2; }
        if (v.w > best) { best = v.w; bi = e + 3; }
    }
    // reduce across the 4 lanes of this row (keep smallest index on ties)
    #pragma unroll
    for (int off = 2; off >= 1; off >>= 1) {
        float ov = __shfl_down_sync(0xFFFFFFFFu, best, off);
        int   oi = __shfl_down_sync(0xFFFFFFFFu, bi,   off);
        if (ov > best || (ov == best && oi < bi)) { best = ov; bi = oi; }
    }
    if (sub == 0 && valid) {
        size_t base = (size_t)b * N + row;
        d_score[base] = best;
        d_label[base] = bi;
        if (best > SCORE_THR) {
            int copy = blockIdx.x & (HCOPY - 1);
            atomicAdd(&d_hist1[(((b * HCOPY) + copy) << 16) + (__float_as_uint(best) >> 16)], 1u);
        }
    }
}

// ---------------- K1 (generic fallback) ----------------
__global__ void scoreKgen(const float* __restrict__ cls, int N, int C) {
    int b = blockIdx.y;
    int n = blockIdx.x * blockDim.x + threadIdx.x;
    if (n >= N) return;
    size_t base = (size_t)b * N + n;
    const float* row = cls + base * C;
    float best = row[0]; int bi = 0;
    for (int k = 1; k < C; k++) { float v = row[k]; if (v > best) { best = v; bi = k; } }
    d_score[base] = best;
    d_label[base] = bi;
    if (best > SCORE_THR) {
        int copy = blockIdx.x & (HCOPY - 1);
        atomicAdd(&d_hist1[(((b * HCOPY) + copy) << 16) + (__float_as_uint(best) >> 16)], 1u);
    }
}

// ---------------- K1b: sum privatized histogram copies (coalesced) ----------------
__global__ void reduceHistK() {
    int i = blockIdx.x * blockDim.x + threadIdx.x;   // over MAXB * NBIN
    if (i >= MAXB * NBIN) return;
    int b = i >> 16, bin = i & 0xFFFF;
    unsigned s = 0;
    #pragma unroll
    for (int c = 0; c < HCOPY; c++)
        s += d_hist1[((b * HCOPY + c) << 16) + bin];
    d_hist1s[i] = s;
}

// ---------------- bin selection: hierarchical suffix scan, 1024 thr/batch ----
// LEVEL 1: h = d_hist1s, target = KPRE       -> writes d_b1, d_rem
// LEVEL 2: h = d_hist2,  target = d_rem[b]   -> writes d_T
template <int LEVEL>
__global__ __launch_bounds__(1024, 1) void selectBinK() {
    __shared__ unsigned cs[256];
    __shared__ unsigned bs[256];
    __shared__ int s_chunk, s_bin;
    __shared__ unsigned s_above1, s_above2;

    int b   = blockIdx.x;
    int tid = threadIdx.x;
    int w   = tid >> 5, l = tid & 31;

    int target;
    const unsigned* H;
    if (LEVEL == 1) {
        target = KPRE;
        H = d_hist1s + b * NBIN;
    } else {
        if (d_b1[b] < 0) { if (tid == 0) d_T[b] = 1u; return; }
        target = d_rem[b];
        H = d_hist2 + b * NBIN;
    }
    if (tid == 0) { s_chunk = -1; s_bin = 0; s_above1 = 0; s_above2 = 0; }

    // --- chunk sums: warp w covers chunks [8w, 8w+8) ---
    #pragma unroll
    for (int cc = 0; cc < 8; cc++) {
        int c = w * 8 + cc;
        unsigned s = 0;
        #pragma unroll
        for (int m = 0; m < 8; m++) s += H[c * 256 + m * 32 + l];
        #pragma unroll
        for (int off = 16; off >= 1; off >>= 1)
            s += __shfl_down_sync(0xFFFFFFFFu, s, off);
        if (l == 0) cs[c] = s;
    }
    __syncthreads();

    // --- suffix scan over 256 chunk sums ---
    #pragma unroll
    for (int off = 1; off < 256; off <<= 1) {
        unsigned v = 0, a = 0;
        if (tid < 256) { v = cs[tid]; a = (tid + off < 256) ? cs[tid + off] : 0u; }
        __syncthreads();
        if (tid < 256) cs[tid] = v + a;
        __syncthreads();
    }
    // crossing chunk: max c with suffix[c] >= target
    if (tid < 256) {
        unsigned sfx = cs[tid];
        unsigned nxt = (tid == 255) ? 0u : cs[tid + 1];
        if (sfx >= (unsigned)target && nxt < (unsigned)target) {
            s_chunk = tid; s_above1 = nxt;
        }
    }
    __syncthreads();

    int c = s_chunk;
    if (c < 0) {                       // total < target (level 1 only)
        if (tid == 0) {
            if (LEVEL == 1) { d_b1[b] = -1; d_rem[b] = 0; }
            else            { d_T[b] = 1u; }
        }
        return;
    }
    int target2 = target - (int)s_above1;

    // --- suffix scan over the 256 bins of chunk c ---
    if (tid < 256) bs[tid] = H[c * 256 + tid];
    __syncthreads();
    #pragma unroll
    for (int off = 1; off < 256; off <<= 1) {
        unsigned v = 0, a = 0;
        if (tid < 256) { v = bs[tid]; a = (tid + off < 256) ? bs[tid + off] : 0u; }
        __syncthreads();
        if (tid < 256) bs[tid] = v + a;
        __syncthreads();
    }
    if (tid < 256) {
        unsigned sfx = bs[tid];
        unsigned nxt = (tid == 255) ? 0u : bs[tid + 1];
        if (sfx >= (unsigned)target2 && nxt < (unsigned)target2) {
            s_bin = tid; s_above2 = nxt;
        }
    }
    __syncthreads();

    if (tid == 0) {
        int bin = c * 256 + s_bin;
        if (LEVEL == 1) {
            d_b1[b]  = bin;
            d_rem[b] = target2 - (int)s_above2;
        } else {
            d_T[b] = (((unsigned)d_b1[b]) << 16) | (unsigned)bin;
        }
    }
}

// ---------------- K3: level-2 histogram (low 16 bits) for items in bin1 ----------------
__global__ void hist2K(int N) {
    int b = blockIdx.y;
    int n = blockIdx.x * blockDim.x + threadIdx.x;
    if (n >= N) return;
    float s = d_score[(size_t)b * N + n];
    if (s > SCORE_THR) {
        unsigned key = __float_as_uint(s);
        if ((int)(key >> 16) == d_b1[b])
            atomicAdd(&d_hist2[(b << 16) + (key & 0xFFFFu)], 1u);
    }
}

// ---------------- K5: gather candidates with key >= T ----------------
__global__ void gatherK(int N) {
    int b = blockIdx.y;
    int n = blockIdx.x * blockDim.x + threadIdx.x;
    if (n >= N) return;
    float s = d_score[(size_t)b * N + n];
    if (s > SCORE_THR) {
        unsigned key = __float_as_uint(s);
        if (key >= d_T[b]) {
            int p = atomicAdd(&d_cnt[b], 1);
            if (p < GCAP)
                d_gath[b * GCAP + p] = ((unsigned long long)key << 32) | (unsigned)(~(unsigned)n);
        }
    }
}

// ---------------- K6: sort candidates, decode+clip boxes, NMS, write output ----------------
__global__ __launch_bounds__(1024, 1) void finalizeK(
    const float* __restrict__ anchors, const float* __restrict__ regs,
    const float* __restrict__ sizes, float* __restrict__ out, int N, int B)
{
    int b = blockIdx.x;
    int tid = threadIdx.x;

    // shared layout (mask region aliases the sort buffer):
    __shared__ __align__(16) unsigned char sm[47296];
    unsigned int*       mask  = (unsigned int*)sm;            // [512][16]
    unsigned long long* arr   = (unsigned long long*)sm;      // [2048]
    float4*             sBox  = (float4*)(sm + 32768);
    float*              sArea = (float*) (sm + 40960);
    float*              sScore= (float*) (sm + 43008);
    int*                sLabel= (int*)   (sm + 45056);
    unsigned int*       keepW = (unsigned int*)(sm + 47104);
    int*                warpCnt = (int*)(sm + 47168);

    int cnt = d_cnt[b]; if (cnt > GCAP) cnt = GCAP;
    int nv  = cnt < KPRE ? cnt : KPRE;
    int S   = (cnt <= 512) ? 512 : ((cnt <= 1024) ? 1024 : 2048);

    for (int i = tid; i < S; i += blockDim.x)
        arr[i] = (i < cnt) ? d_gath[b * GCAP + i] : 0ull;
    __syncthreads();

    // bitonic sort, S elems descending (key desc, idx asc)
    for (int k = 2; k <= S; k <<= 1) {
        for (int j = k >> 1; j >= 1; j >>= 1) {
            if (tid < (S >> 1)) {
                int i = ((tid & ~(j - 1)) << 1) | (tid & (j - 1));
                int p = i + j;
                bool up = (i & k) != 0;
                unsigned long long a = arr[i], c2 = arr[p];
                bool sw = up ? (a > c2) : (a < c2);
                if (sw) { arr[i] = c2; arr[p] = a; }
            }
            __syncthreads();
        }
    }

    // decode + clip boxes for top nv; default-fill output with -1
    float H = sizes[b * 2 + 0], W = sizes[b * 2 + 1];
    if (tid < nv) {
        unsigned long long v = arr[tid];
        unsigned key = (unsigned)(v >> 32);
        int idx = (int)(~(unsigned)v);
        size_t off = (size_t)b * N + idx;
        float4 a = ((const float4*)anchors)[off];
        float4 r = ((const float4*)regs)[off];
        float w = a.z - a.x, h = a.w - a.y;
        float cx = a.x + 0.5f * w, cy = a.y + 0.5f * h;
        float dx = r.x * 0.1f, dy = r.y * 0.1f, dw = r.z * 0.2f, dh = r.w * 0.2f;
        float pcx = cx + dx * w, pcy = cy + dy * h;
        float pw = expf(dw) * w, ph = expf(dh) * h;
        float x1 = pcx - 0.5f * pw, y1 = pcy - 0.5f * ph;
        float x2 = pcx + 0.5f * pw, y2 = pcy + 0.5f * ph;
        x1 = fminf(fmaxf(x1, 0.f), W); x2 = fminf(fmaxf(x2, 0.f), W);
        y1 = fminf(fmaxf(y1, 0.f), H); y2 = fminf(fmaxf(y2, 0.f), H);
        sBox[tid]  = make_float4(x1, y1, x2, y2);
        sArea[tid] = (x2 - x1) * (y2 - y1);
        sScore[tid]= __uint_as_float(key);
        sLabel[tid]= d_label[off];
    }
    float* outB = out;
    float* outS = out + (size_t)B * MAXDET * 4;
    float* outL = out + (size_t)B * MAXDET * 5;
    if (tid < MAXDET) {
        ((float4*)outB)[b * MAXDET + tid] = make_float4(-1.f, -1.f, -1.f, -1.f);
        outS[b * MAXDET + tid] = -1.f;
        outL[b * MAXDET + tid] = -1.f;
    }
    __syncthreads();   // arr reads done -> mask may now overwrite that region

    // parallel IoU suppression bitmask (division-free compare):
    // inter/(ai+aj-inter+eps) > thr  <=>  inter*(1+thr) > thr*(ai+aj+eps)
    if (tid < KPRE) {
        float4 bi; float ai = 0.f;
        bool v = tid < nv;
        if (v) { bi = sBox[tid]; ai = sArea[tid]; }
        for (int w = 0; w < 16; w++) {
            unsigned word = 0;
            if (v) {
                int j0 = w * 32, j1 = j0 + 32;
                if (j1 > nv) j1 = nv;
                int js = (tid + 1 > j0) ? tid + 1 : j0;
                for (int j = js; j < j1; j++) {
                    float4 bj = sBox[j];
                    float lx = fmaxf(bi.x, bj.x), ly = fmaxf(bi.y, bj.y);
                    float rx = fminf(bi.z, bj.z), ry = fminf(bi.w, bj.w);
                    float iw = fmaxf(rx - lx, 0.f), ih = fmaxf(ry - ly, 0.f);
                    float inter = iw * ih;
                    float lhs = inter * (1.0f + IOU_THR);
                    float rhs = IOU_THR * (ai + sArea[j] + 1e-9f);
                    if (lhs > rhs) word |= 1u << (j & 31);
                }
            }
            mask[tid * 16 + w] = word;
        }
    }
    __syncthreads();

    // warp-serial greedy resolution, keep-words live in registers
    if (tid < 32) {
        unsigned kw = 0;
        if (tid < 16) {
            int full = nv >> 5, rem = nv & 31;
            kw = (tid < full) ? 0xFFFFFFFFu
               : ((tid == full && rem) ? ((1u << rem) - 1u) : 0u);
        }
        for (int i = 0; i < nv; i++) {
            unsigned ow = __shfl_sync(0xFFFFFFFFu, kw, i >> 5);
            if ((ow >> (i & 31)) & 1u) {
                if (tid < 16) kw &= ~mask[i * 16 + tid];
            }
        }
        if (tid < 16) keepW[tid] = kw;
    }
    __syncthreads();

    // compact kept candidates (score order) into first <=300 slots
    bool kept = false;
    if (tid < nv) kept = (keepW[tid >> 5] >> (tid & 31)) & 1u;
    unsigned wm = __ballot_sync(0xFFFFFFFFu, kept);
    int w = tid >> 5, lane = tid & 31;
    if (lane == 0) warpCnt[w] = __popc(wm);
    __syncthreads();
    if (kept) {
        int prefix = 0;
        for (int i = 0; i < w; i++) prefix += warpCnt[i];
        int pos = prefix + __popc(wm & ((1u << lane) - 1u));
        if (pos < MAXDET) {
            ((float4*)outB)[b * MAXDET + pos] = sBox[tid];
            outS[b * MAXDET + pos] = sScore[tid];
            outL[b * MAXDET + pos] = (float)sLabel[tid];
        }
    }
}

// ---------------- launch ----------------
extern "C" void kernel_launch(void* const* d_in, const int* in_sizes, int n_in,
                              void* d_out, int out_size) {
    const float* anchors = (const float*)d_in[0];
    const float* regs    = (const float*)d_in[1];
    const float* cls     = (const float*)d_in[2];
    const float* sizes   = (const float*)d_in[3];

    int B = in_sizes[3] / 2;            // sizes is [B,2]
    if (B <= 0 || B > MAXB) B = MAXB;
    int N = in_sizes[0] / (B * 4);      // anchors [B,N,4]
    long long clsElems = (long long)in_sizes[2];
    int C = (int)(clsElems / ((long long)B * N));

    dim3 gridBN((N + 255) / 256, B);

    zeroK<<<(MAXB * HCOPY * NBIN + 255) / 256, 256>>>();
    if (C == 80) {
        dim3 gridS(((N * 4) + 255) / 256, B);
        scoreK80<<<gridS, 256>>>(cls, N);
    } else {
        scoreKgen<<<gridBN, 256>>>(cls, N, C);
    }
    reduceHistK<<<(MAXB * NBIN + 255) / 256, 256>>>();
    selectBinK<1><<<B, 1024>>>();
    hist2K<<<gridBN, 256>>>(N);
    selectBinK<2><<<B, 1024>>>();
    gatherK<<<gridBN, 256>>>(N);
    finalizeK<<<B, 1024>>>(anchors, regs, sizes, (float*)d_out, N, B);
}